// round 2
// baseline (speedup 1.0000x reference)
#include <cuda_runtime.h>
#include <math.h>

#define Bz 2
#define Sz 2048
#define Dz 1024
#define Hz 16
#define DHz 64
#define NROW (Bz*Sz)   // 4096

// Scratch (no allocations allowed)
__device__ float g_q[Bz*Hz*Sz*DHz];      // [B,H,S,DH]
__device__ float g_k[Bz*Hz*Sz*DHz];
__device__ float g_v[Bz*Hz*Sz*DHz];
__device__ float g_attn[Bz*Sz*Dz];       // merged heads [B,S,D]

// ---------------------------------------------------------------------------
// Projection GEMM:  Y = X @ W^T + b  (M=4096, N=1024, K=1024), NT layout,
// writes split-head layout into g_q/g_k/g_v selected by `which`.
// BM=BN=128, BK=8, 256 threads, 8x8 microtile.
// ---------------------------------------------------------------------------
__global__ __launch_bounds__(256)
void proj_kernel(const float* __restrict__ X,
                 const float* __restrict__ Wm,
                 const float* __restrict__ bias,
                 int which)
{
    const int K = Dz;
    __shared__ float As[8][128];
    __shared__ float Bs[8][128];
    const int tid = threadIdx.x;
    const int bm = blockIdx.y * 128;
    const int bn = blockIdx.x * 128;
    const int tx = tid & 15;
    const int ty = tid >> 4;
    const int lr = tid >> 1;
    const int lc = (tid & 1) * 4;

    float acc[8][8];
#pragma unroll
    for (int i = 0; i < 8; i++)
#pragma unroll
        for (int j = 0; j < 8; j++) acc[i][j] = 0.f;

    const float* Aptr = X  + (size_t)(bm + lr) * K + lc;
    const float* Bptr = Wm + (size_t)(bn + lr) * K + lc;

    for (int k0 = 0; k0 < K; k0 += 8) {
        float4 a4 = *(const float4*)(Aptr + k0);
        float4 b4 = *(const float4*)(Bptr + k0);
        As[lc+0][lr] = a4.x; As[lc+1][lr] = a4.y; As[lc+2][lr] = a4.z; As[lc+3][lr] = a4.w;
        Bs[lc+0][lr] = b4.x; Bs[lc+1][lr] = b4.y; Bs[lc+2][lr] = b4.z; Bs[lc+3][lr] = b4.w;
        __syncthreads();
#pragma unroll
        for (int k = 0; k < 8; k++) {
            float4 a0 = *(const float4*)&As[k][ty*8];
            float4 a1 = *(const float4*)&As[k][ty*8+4];
            float4 b0 = *(const float4*)&Bs[k][tx*8];
            float4 b1 = *(const float4*)&Bs[k][tx*8+4];
            float ar[8] = {a0.x,a0.y,a0.z,a0.w,a1.x,a1.y,a1.z,a1.w};
            float br[8] = {b0.x,b0.y,b0.z,b0.w,b1.x,b1.y,b1.z,b1.w};
#pragma unroll
            for (int i = 0; i < 8; i++)
#pragma unroll
                for (int j = 0; j < 8; j++)
                    acc[i][j] += ar[i] * br[j];
        }
        __syncthreads();
    }

    float* dst = (which == 0) ? g_q : (which == 1) ? g_k : g_v;
#pragma unroll
    for (int i = 0; i < 8; i++) {
        int row = bm + ty*8 + i;          // b*S + s
        int b = row >> 11;
        int s = row & (Sz - 1);
#pragma unroll
        for (int j = 0; j < 8; j++) {
            int col = bn + tx*8 + j;      // h*DH + dh
            int h  = col >> 6;
            int dh = col & (DHz - 1);
            float val = acc[i][j] + bias[col];
            dst[(((size_t)b*Hz + h)*Sz + s)*DHz + dh] = val;
        }
    }
}

// ---------------------------------------------------------------------------
// Scores:  S[bh,i,j] = scale * dot(Q[bh,i,:], K[bh,j,:]) masked -> weights buf
// K=64. BM=BN=128, BK=8. grid (16,16,32)
// ---------------------------------------------------------------------------
__global__ __launch_bounds__(256)
void scores_kernel(const int* __restrict__ mask,
                   float* __restrict__ Wout)
{
    __shared__ float As[8][128];
    __shared__ float Bs[8][128];
    const int bh = blockIdx.z;
    const int b = bh >> 4;
    const float* A  = g_q + (size_t)bh * Sz * DHz;
    const float* Bm = g_k + (size_t)bh * Sz * DHz;

    const int tid = threadIdx.x;
    const int bm = blockIdx.y * 128;
    const int bn = blockIdx.x * 128;
    const int tx = tid & 15;
    const int ty = tid >> 4;
    const int lr = tid >> 1;
    const int lc = (tid & 1) * 4;

    float acc[8][8];
#pragma unroll
    for (int i = 0; i < 8; i++)
#pragma unroll
        for (int j = 0; j < 8; j++) acc[i][j] = 0.f;

    const float* Aptr = A  + (size_t)(bm + lr) * DHz + lc;
    const float* Bptr = Bm + (size_t)(bn + lr) * DHz + lc;

    for (int k0 = 0; k0 < DHz; k0 += 8) {
        float4 a4 = *(const float4*)(Aptr + k0);
        float4 b4 = *(const float4*)(Bptr + k0);
        As[lc+0][lr] = a4.x; As[lc+1][lr] = a4.y; As[lc+2][lr] = a4.z; As[lc+3][lr] = a4.w;
        Bs[lc+0][lr] = b4.x; Bs[lc+1][lr] = b4.y; Bs[lc+2][lr] = b4.z; Bs[lc+3][lr] = b4.w;
        __syncthreads();
#pragma unroll
        for (int k = 0; k < 8; k++) {
            float4 a0 = *(const float4*)&As[k][ty*8];
            float4 a1 = *(const float4*)&As[k][ty*8+4];
            float4 b0 = *(const float4*)&Bs[k][tx*8];
            float4 b1 = *(const float4*)&Bs[k][tx*8+4];
            float ar[8] = {a0.x,a0.y,a0.z,a0.w,a1.x,a1.y,a1.z,a1.w};
            float br[8] = {b0.x,b0.y,b0.z,b0.w,b1.x,b1.y,b1.z,b1.w};
#pragma unroll
            for (int i = 0; i < 8; i++)
#pragma unroll
                for (int j = 0; j < 8; j++)
                    acc[i][j] += ar[i] * br[j];
        }
        __syncthreads();
    }

    const float scale = 0.125f;   // 1/sqrt(64)
    const float ninf = -INFINITY;
#pragma unroll
    for (int i = 0; i < 8; i++) {
        int row = bm + ty*8 + i;
        const int*  mrow = mask + (size_t)b*Sz*Sz + (size_t)row*Sz;
        float* wrow = Wout + ((size_t)bh*Sz + row)*Sz;
#pragma unroll
        for (int j = 0; j < 8; j++) {
            int col = bn + tx*8 + j;
            wrow[col] = mrow[col] ? acc[i][j]*scale : ninf;
        }
    }
}

// ---------------------------------------------------------------------------
// Row softmax in-place on weights buffer. One block (256 thr) per row of 2048.
// ---------------------------------------------------------------------------
__global__ __launch_bounds__(256)
void softmax_kernel(float* __restrict__ Wt)
{
    const size_t row = blockIdx.x;
    float4* w4 = (float4*)(Wt + row * (size_t)Sz);
    const int tid = threadIdx.x;
    const int lane = tid & 31, wid = tid >> 5;

    float4 x0 = w4[tid];
    float4 x1 = w4[tid + 256];

    float mx = fmaxf(fmaxf(fmaxf(x0.x, x0.y), fmaxf(x0.z, x0.w)),
                     fmaxf(fmaxf(x1.x, x1.y), fmaxf(x1.z, x1.w)));
    __shared__ float red[8];
#pragma unroll
    for (int o = 16; o > 0; o >>= 1)
        mx = fmaxf(mx, __shfl_xor_sync(0xffffffffu, mx, o));
    if (lane == 0) red[wid] = mx;
    __syncthreads();
    if (tid < 32) {
        float v = (lane < 8) ? red[lane] : -INFINITY;
#pragma unroll
        for (int o = 4; o > 0; o >>= 1)
            v = fmaxf(v, __shfl_xor_sync(0xffffffffu, v, o));
        if (lane == 0) red[0] = v;
    }
    __syncthreads();
    const float m = red[0];

    x0.x = expf(x0.x - m); x0.y = expf(x0.y - m);
    x0.z = expf(x0.z - m); x0.w = expf(x0.w - m);
    x1.x = expf(x1.x - m); x1.y = expf(x1.y - m);
    x1.z = expf(x1.z - m); x1.w = expf(x1.w - m);

    float sm = x0.x + x0.y + x0.z + x0.w + x1.x + x1.y + x1.z + x1.w;
#pragma unroll
    for (int o = 16; o > 0; o >>= 1)
        sm += __shfl_xor_sync(0xffffffffu, sm, o);
    __syncthreads();                    // red reuse
    if (lane == 0) red[wid] = sm;
    __syncthreads();
    if (tid < 32) {
        float v = (lane < 8) ? red[lane] : 0.f;
#pragma unroll
        for (int o = 4; o > 0; o >>= 1)
            v += __shfl_xor_sync(0xffffffffu, v, o);
        if (lane == 0) red[0] = v;
    }
    __syncthreads();
    const float inv = 1.0f / red[0];

    x0.x *= inv; x0.y *= inv; x0.z *= inv; x0.w *= inv;
    x1.x *= inv; x1.y *= inv; x1.z *= inv; x1.w *= inv;
    w4[tid] = x0;
    w4[tid + 256] = x1;
}

// ---------------------------------------------------------------------------
// AV:  out[bh,i,d] = sum_j W[bh,i,j] * V[bh,j,d]  -> merged-head g_attn
// NN layout. BM=128, BN=64(=DH), BK=16, 256 threads, 8x4 microtile.
// grid (1, 16, 32)
// ---------------------------------------------------------------------------
__global__ __launch_bounds__(256)
void av_kernel(const float* __restrict__ Wt)
{
    __shared__ float As[16][128];   // 8 KB
    __shared__ float Bs[16][64];    // 4 KB
    const int bh = blockIdx.z;
    const int b = bh >> 4;
    const int h = bh & (Hz - 1);
    const float* A  = Wt  + (size_t)bh * Sz * Sz;   // [S,S] probs
    const float* Bm = g_v + (size_t)bh * Sz * DHz;  // [S,64]
    const int bm = blockIdx.y * 128;
    const int tid = threadIdx.x;
    const int tx = tid & 15;
    const int ty = tid >> 4;

    float acc[8][4];
#pragma unroll
    for (int i = 0; i < 8; i++)
#pragma unroll
        for (int j = 0; j < 4; j++) acc[i][j] = 0.f;

    for (int k0 = 0; k0 < Sz; k0 += 16) {
        // A tile: 128 x 16 (k-contig), 512 float4, 2 per thread
#pragma unroll
        for (int q = 0; q < 2; q++) {
            int f = tid*2 + q;
            int row = f >> 2;
            int kq = (f & 3) * 4;
            float4 a4 = *(const float4*)(A + (size_t)(bm + row)*Sz + k0 + kq);
            As[kq+0][row] = a4.x; As[kq+1][row] = a4.y;
            As[kq+2][row] = a4.z; As[kq+3][row] = a4.w;
        }
        // B tile: 16 x 64 (n-contig), 256 float4, 1 per thread
        {
            int kk  = tid >> 4;
            int col = (tid & 15) * 4;
            *(float4*)&Bs[kk][col] =
                *(const float4*)(Bm + (size_t)(k0 + kk)*DHz + col);
        }
        __syncthreads();
#pragma unroll
        for (int k = 0; k < 16; k++) {
            float4 a0 = *(const float4*)&As[k][ty*8];
            float4 a1 = *(const float4*)&As[k][ty*8+4];
            float4 b0 = *(const float4*)&Bs[k][tx*4];
            float ar[8] = {a0.x,a0.y,a0.z,a0.w,a1.x,a1.y,a1.z,a1.w};
            float br[4] = {b0.x,b0.y,b0.z,b0.w};
#pragma unroll
            for (int i = 0; i < 8; i++)
#pragma unroll
                for (int j = 0; j < 4; j++)
                    acc[i][j] += ar[i] * br[j];
        }
        __syncthreads();
    }
#pragma unroll
    for (int i = 0; i < 8; i++) {
        int row = bm + ty*8 + i;    // sequence index within (b)
        float* orow = g_attn + ((size_t)b*Sz + row)*Dz + h*DHz;
#pragma unroll
        for (int j = 0; j < 4; j++)
            orow[tx*4 + j] = acc[i][j];
    }
}

// ---------------------------------------------------------------------------
// Dense:  out = g_attn @ dense_w^T + dense_b  (M=4096,N=1024,K=1024), NT
// ---------------------------------------------------------------------------
__global__ __launch_bounds__(256)
void dense_kernel(const float* __restrict__ Wm,
                  const float* __restrict__ bias,
                  float* __restrict__ C)
{
    const int K = Dz, N = Dz;
    __shared__ float As[8][128];
    __shared__ float Bs[8][128];
    const int tid = threadIdx.x;
    const int bm = blockIdx.y * 128;
    const int bn = blockIdx.x * 128;
    const int tx = tid & 15;
    const int ty = tid >> 4;
    const int lr = tid >> 1;
    const int lc = (tid & 1) * 4;

    float acc[8][8];
#pragma unroll
    for (int i = 0; i < 8; i++)
#pragma unroll
        for (int j = 0; j < 8; j++) acc[i][j] = 0.f;

    const float* Aptr = g_attn + (size_t)(bm + lr) * K + lc;
    const float* Bptr = Wm     + (size_t)(bn + lr) * K + lc;

    for (int k0 = 0; k0 < K; k0 += 8) {
        float4 a4 = *(const float4*)(Aptr + k0);
        float4 b4 = *(const float4*)(Bptr + k0);
        As[lc+0][lr] = a4.x; As[lc+1][lr] = a4.y; As[lc+2][lr] = a4.z; As[lc+3][lr] = a4.w;
        Bs[lc+0][lr] = b4.x; Bs[lc+1][lr] = b4.y; Bs[lc+2][lr] = b4.z; Bs[lc+3][lr] = b4.w;
        __syncthreads();
#pragma unroll
        for (int k = 0; k < 8; k++) {
            float4 a0 = *(const float4*)&As[k][ty*8];
            float4 a1 = *(const float4*)&As[k][ty*8+4];
            float4 b0 = *(const float4*)&Bs[k][tx*8];
            float4 b1 = *(const float4*)&Bs[k][tx*8+4];
            float ar[8] = {a0.x,a0.y,a0.z,a0.w,a1.x,a1.y,a1.z,a1.w};
            float br[8] = {b0.x,b0.y,b0.z,b0.w,b1.x,b1.y,b1.z,b1.w};
#pragma unroll
            for (int i = 0; i < 8; i++)
#pragma unroll
                for (int j = 0; j < 8; j++)
                    acc[i][j] += ar[i] * br[j];
        }
        __syncthreads();
    }
#pragma unroll
    for (int i = 0; i < 8; i++) {
        int row = bm + ty*8 + i;
#pragma unroll
        for (int j = 0; j < 8; j++) {
            int col = bn + tx*8 + j;
            C[(size_t)row*N + col] = acc[i][j] + bias[col];
        }
    }
}

// ---------------------------------------------------------------------------
extern "C" void kernel_launch(void* const* d_in, const int* in_sizes, int n_in,
                              void* d_out, int out_size)
{
    const float* q    = (const float*)d_in[0];
    const float* k    = (const float*)d_in[1];
    const float* v    = (const float*)d_in[2];
    const int*   mask = (const int*)  d_in[3];
    const float* wq_w = (const float*)d_in[4];
    const float* wq_b = (const float*)d_in[5];
    const float* wk_w = (const float*)d_in[6];
    const float* wk_b = (const float*)d_in[7];
    const float* wv_w = (const float*)d_in[8];
    const float* wv_b = (const float*)d_in[9];
    const float* dw   = (const float*)d_in[10];
    const float* db   = (const float*)d_in[11];

    float* out     = (float*)d_out;                       // [B,S,D]
    float* weights = out + (size_t)Bz * Sz * Dz;          // [B,H,S,S]

    dim3 blk(256);
    dim3 gProj(Dz/128, NROW/128);          // (8, 32)
    proj_kernel<<<gProj, blk>>>(q, wq_w, wq_b, 0);
    proj_kernel<<<gProj, blk>>>(k, wk_w, wk_b, 1);
    proj_kernel<<<gProj, blk>>>(v, wv_w, wv_b, 2);

    dim3 gSc(Sz/128, Sz/128, Bz*Hz);       // (16, 16, 32)
    scores_kernel<<<gSc, blk>>>(mask, weights);

    softmax_kernel<<<Bz*Hz*Sz, blk>>>(weights);

    dim3 gAv(1, Sz/128, Bz*Hz);            // (1, 16, 32)
    av_kernel<<<gAv, blk>>>(weights);

    dim3 gDn(Dz/128, NROW/128);            // (8, 32)
    dense_kernel<<<gDn, blk>>>(dw, db, out);
}

// round 4
// speedup vs baseline: 2.4265x; 2.4265x over previous
#include <cuda_runtime.h>
#include <cuda_bf16.h>
#include <cstdint>
#include <math.h>

#define Bz 2
#define Sz 2048
#define Dz 1024
#define Hz 16
#define DHz 64
#define NROW (Bz*Sz)   // 4096

// ---------------- device scratch (no allocations allowed) -------------------
__device__ float g_q[Bz*Hz*Sz*DHz];       // [B,H,S,DH]
__device__ float g_k[Bz*Hz*Sz*DHz];       // [B,H,S,DH]
__device__ float g_vt[Bz*Hz*DHz*Sz];      // [B,H,DH,S]  (transposed V)
__device__ float g_attn[Bz*Sz*Dz];        // merged heads [B,S,D]

// ---------------- helpers ---------------------------------------------------
__device__ __forceinline__ uint32_t packbf(float a, float b){
    __nv_bfloat162 t = __floats2bfloat162_rn(a, b);
    return *reinterpret_cast<uint32_t*>(&t);
}

// x = hi + lo split, packed into bf16x2 words (consecutive-k pairs)
__device__ __forceinline__ void split4(float4 x, uint32_t& h0, uint32_t& h1,
                                       uint32_t& l0, uint32_t& l1){
    float hx = __bfloat162float(__float2bfloat16(x.x));
    float hy = __bfloat162float(__float2bfloat16(x.y));
    float hz = __bfloat162float(__float2bfloat16(x.z));
    float hw = __bfloat162float(__float2bfloat16(x.w));
    h0 = packbf(hx, hy);
    h1 = packbf(hz, hw);
    l0 = packbf(x.x - hx, x.y - hy);
    l1 = packbf(x.z - hz, x.w - hw);
}

__device__ __forceinline__ void mma16816(float* d, const uint32_t* a, const uint32_t* b){
    asm volatile("mma.sync.aligned.m16n8k16.row.col.f32.bf16.bf16.f32 "
        "{%0,%1,%2,%3}, {%4,%5,%6,%7}, {%8,%9}, {%0,%1,%2,%3};"
        : "+f"(d[0]), "+f"(d[1]), "+f"(d[2]), "+f"(d[3])
        : "r"(a[0]), "r"(a[1]), "r"(a[2]), "r"(a[3]), "r"(b[0]), "r"(b[1]));
}

// ---------------- GEMM mainloop (NT): C += A[M,K] * B[N,K]^T ---------------
// BM=128 fixed, BN in {128,64}, BK=32, 256 threads, warp grid 2(m) x 4(n).
// Smem rows padded to 40 bf16 (20 words) -> conflict-free fragment loads.
template<int BN>
__device__ __forceinline__ void gemm_bf16(
    const float* __restrict__ A, int lda,
    const float* __restrict__ B, int ldb, int K,
    uint32_t* sm, float acc[4][BN/32][4], int tid)
{
    constexpr int N_AT = BN/32;
    constexpr int AW = 20;                 // words per padded row
    constexpr int ATw = 128*AW;
    constexpr int BTw = BN*AW;
    constexpr int STG = 2*ATw + 2*BTw;     // words per stage
    const int wid = tid>>5, lane = tid&31;
    const int wm = (wid>>2)*64;
    const int wn = (wid&3)*(BN/4);
    const int gid = lane>>2, qid = lane&3;
    const int NC = K/32;

    float4 pa[4];
    float4 pb[N_AT];

    auto ldga = [&](int c){
#pragma unroll
        for (int i=0;i<4;i++){
            int f = i*256+tid, row = f>>3, c4 = f&7;
            pa[i] = *(const float4*)(A + (size_t)row*lda + c*32 + c4*4);
        }
#pragma unroll
        for (int i=0;i<N_AT;i++){
            int f = i*256+tid, row = f>>3, c4 = f&7;
            pb[i] = *(const float4*)(B + (size_t)row*ldb + c*32 + c4*4);
        }
    };
    auto sts = [&](int s){
        uint32_t* Ah = sm + s*STG;
        uint32_t* Al = Ah + ATw;
        uint32_t* Bh = Al + ATw;
        uint32_t* Bl = Bh + BTw;
#pragma unroll
        for (int i=0;i<4;i++){
            int f = i*256+tid, row = f>>3, c4 = f&7;
            uint32_t h0,h1,l0,l1; split4(pa[i],h0,h1,l0,l1);
            Ah[row*AW + c4*2]   = h0; Ah[row*AW + c4*2+1] = h1;
            Al[row*AW + c4*2]   = l0; Al[row*AW + c4*2+1] = l1;
        }
#pragma unroll
        for (int i=0;i<N_AT;i++){
            int f = i*256+tid, row = f>>3, c4 = f&7;
            uint32_t h0,h1,l0,l1; split4(pb[i],h0,h1,l0,l1);
            Bh[row*AW + c4*2]   = h0; Bh[row*AW + c4*2+1] = h1;
            Bl[row*AW + c4*2]   = l0; Bl[row*AW + c4*2+1] = l1;
        }
    };

    ldga(0); sts(0); __syncthreads();

    for (int c = 0; c < NC; c++){
        int cur = c & 1;
        if (c+1 < NC) ldga(c+1);

        const uint32_t* Ah = sm + cur*STG;
        const uint32_t* Al = Ah + ATw;
        const uint32_t* Bh = Al + ATw;
        const uint32_t* Bl = Bh + BTw;
#pragma unroll
        for (int c16 = 0; c16 < 2; c16++){
            uint32_t aH[4][4], aL[4][4];
            const int w0 = c16*8 + qid;
#pragma unroll
            for (int mi=0;mi<4;mi++){
                int r0 = wm + mi*16 + gid;
                aH[mi][0]=Ah[r0*AW+w0];    aH[mi][1]=Ah[(r0+8)*AW+w0];
                aH[mi][2]=Ah[r0*AW+w0+4];  aH[mi][3]=Ah[(r0+8)*AW+w0+4];
                aL[mi][0]=Al[r0*AW+w0];    aL[mi][1]=Al[(r0+8)*AW+w0];
                aL[mi][2]=Al[r0*AW+w0+4];  aL[mi][3]=Al[(r0+8)*AW+w0+4];
            }
            uint32_t bH[N_AT][2], bL[N_AT][2];
#pragma unroll
            for (int ni=0;ni<N_AT;ni++){
                int rn = wn + ni*8 + gid;
                bH[ni][0]=Bh[rn*AW+w0]; bH[ni][1]=Bh[rn*AW+w0+4];
                bL[ni][0]=Bl[rn*AW+w0]; bL[ni][1]=Bl[rn*AW+w0+4];
            }
#pragma unroll
            for (int mi=0;mi<4;mi++)
#pragma unroll
                for (int ni=0;ni<N_AT;ni++){
                    mma16816(acc[mi][ni], aH[mi], bH[ni]);
                    mma16816(acc[mi][ni], aH[mi], bL[ni]);
                    mma16816(acc[mi][ni], aL[mi], bH[ni]);
                }
        }
        __syncthreads();
        if (c+1 < NC){ sts((c+1)&1); __syncthreads(); }
    }
}

// stage accumulators -> fp32 smem tile [128][BN+4], optional scale/bias
template<int BN>
__device__ __forceinline__ void stage_acc(float* stg, float acc[4][BN/32][4],
                                          int tid, float scale, const float* bias_s)
{
    constexpr int SW = BN + 4;
    const int wid = tid>>5, lane = tid&31;
    const int wm = (wid>>2)*64, wn = (wid&3)*(BN/4);
    const int gid = lane>>2, qid = lane&3;
#pragma unroll
    for (int mi=0;mi<4;mi++)
#pragma unroll
        for (int ni=0;ni<BN/32;ni++){
            int r = wm + mi*16 + gid;
            int cc = wn + ni*8 + qid*2;
            float b0 = bias_s ? bias_s[cc]   : 0.f;
            float b1 = bias_s ? bias_s[cc+1] : 0.f;
            stg[(size_t)r*SW + cc]       = acc[mi][ni][0]*scale + b0;
            stg[(size_t)r*SW + cc+1]     = acc[mi][ni][1]*scale + b1;
            stg[(size_t)(r+8)*SW + cc]   = acc[mi][ni][2]*scale + b0;
            stg[(size_t)(r+8)*SW + cc+1] = acc[mi][ni][3]*scale + b1;
        }
}

#define ZERO_ACC(a, NAT) \
    _Pragma("unroll") for (int _i=0;_i<4;_i++) \
    _Pragma("unroll") for (int _j=0;_j<NAT;_j++) \
    _Pragma("unroll") for (int _k=0;_k<4;_k++) a[_i][_j][_k] = 0.f;

// ---------------- projection: Y = X @ W^T + b ------------------------------
__global__ __launch_bounds__(256)
void proj_tc(const float* __restrict__ X, const float* __restrict__ Wm,
             const float* __restrict__ bias, int which)
{
    extern __shared__ uint32_t sm[];
    __shared__ float bias_s[128];
    const int tid = threadIdx.x;
    const int bn = blockIdx.x*128, bm = blockIdx.y*128;
    if (tid < 128) bias_s[tid] = bias[bn + tid];

    float acc[4][4][4]; ZERO_ACC(acc, 4);
    gemm_bf16<128>(X + (size_t)bm*Dz, Dz, Wm + (size_t)bn*Dz, Dz, Dz, sm, acc, tid);

    float* stg = (float*)sm;
    stage_acc<128>(stg, acc, tid, 1.f, bias_s);
    __syncthreads();

    if (which == 2){
        // transposed copy -> g_vt[b,h,dh,s]; lanes walk r (=s) for coalescing
        for (int i=0;i<64;i++){
            int idx = i*256 + tid;
            int r = idx & 127, c = idx >> 7;
            float v = stg[(size_t)r*132 + c];
            int m = bm + r, b = m>>11, s = m & 2047;
            int col = bn + c, h = col>>6, dh = col&63;
            g_vt[(((size_t)b*Hz + h)*DHz + dh)*Sz + s] = v;
        }
    } else {
        float* dst = which ? g_k : g_q;
        for (int i=0;i<16;i++){
            int f = i*256 + tid, r = f>>5, c4 = f&31;
            float4 v = *(float4*)&stg[(size_t)r*132 + c4*4];
            int m = bm + r, b = m>>11, s = m & 2047;
            int col = bn + c4*4, h = col>>6, dh = col&63;
            *(float4*)&dst[(((size_t)b*Hz + h)*Sz + s)*DHz + dh] = v;
        }
    }
}

// ---------------- scores: masked scaled QK^T -> weights --------------------
__global__ __launch_bounds__(256)
void scores_tc(const int* __restrict__ mask, float* __restrict__ Wout)
{
    extern __shared__ uint32_t sm[];
    const int tid = threadIdx.x;
    const int bh = blockIdx.z, b = bh>>4;
    const int bn = blockIdx.x*128, bm = blockIdx.y*128;

    float acc[4][4][4]; ZERO_ACC(acc, 4);
    gemm_bf16<128>(g_q + ((size_t)bh*Sz + bm)*DHz, DHz,
                   g_k + ((size_t)bh*Sz + bn)*DHz, DHz, DHz, sm, acc, tid);

    float* stg = (float*)sm;
    stage_acc<128>(stg, acc, tid, 0.125f, nullptr);
    __syncthreads();

    for (int i=0;i<16;i++){
        int f = i*256 + tid, r = f>>5, c4 = f&31;
        float4 v = *(float4*)&stg[(size_t)r*132 + c4*4];
        int ii = bm + r, col = bn + c4*4;
        int4 mk = *(const int4*)(mask + ((size_t)b*Sz + ii)*Sz + col);
        v.x = mk.x ? v.x : -INFINITY;
        v.y = mk.y ? v.y : -INFINITY;
        v.z = mk.z ? v.z : -INFINITY;
        v.w = mk.w ? v.w : -INFINITY;
        *(float4*)&Wout[((size_t)bh*Sz + ii)*Sz + col] = v;
    }
}

// ---------------- softmax ---------------------------------------------------
__global__ __launch_bounds__(256)
void softmax_kernel(float* __restrict__ Wt)
{
    const size_t row = blockIdx.x;
    float4* w4 = (float4*)(Wt + row * (size_t)Sz);
    const int tid = threadIdx.x;
    const int lane = tid & 31, wid = tid >> 5;

    float4 x0 = w4[tid];
    float4 x1 = w4[tid + 256];

    float mx = fmaxf(fmaxf(fmaxf(x0.x, x0.y), fmaxf(x0.z, x0.w)),
                     fmaxf(fmaxf(x1.x, x1.y), fmaxf(x1.z, x1.w)));
    __shared__ float red[8];
#pragma unroll
    for (int o = 16; o > 0; o >>= 1)
        mx = fmaxf(mx, __shfl_xor_sync(0xffffffffu, mx, o));
    if (lane == 0) red[wid] = mx;
    __syncthreads();
    if (tid < 32) {
        float v = (lane < 8) ? red[lane] : -INFINITY;
#pragma unroll
        for (int o = 4; o > 0; o >>= 1)
            v = fmaxf(v, __shfl_xor_sync(0xffffffffu, v, o));
        if (lane == 0) red[0] = v;
    }
    __syncthreads();
    const float m = red[0];

    x0.x = expf(x0.x - m); x0.y = expf(x0.y - m);
    x0.z = expf(x0.z - m); x0.w = expf(x0.w - m);
    x1.x = expf(x1.x - m); x1.y = expf(x1.y - m);
    x1.z = expf(x1.z - m); x1.w = expf(x1.w - m);

    float sm = x0.x + x0.y + x0.z + x0.w + x1.x + x1.y + x1.z + x1.w;
#pragma unroll
    for (int o = 16; o > 0; o >>= 1)
        sm += __shfl_xor_sync(0xffffffffu, sm, o);
    __syncthreads();
    if (lane == 0) red[wid] = sm;
    __syncthreads();
    if (tid < 32) {
        float v = (lane < 8) ? red[lane] : 0.f;
#pragma unroll
        for (int o = 4; o > 0; o >>= 1)
            v += __shfl_xor_sync(0xffffffffu, v, o);
        if (lane == 0) red[0] = v;
    }
    __syncthreads();
    const float inv = 1.0f / red[0];

    x0.x *= inv; x0.y *= inv; x0.z *= inv; x0.w *= inv;
    x1.x *= inv; x1.y *= inv; x1.z *= inv; x1.w *= inv;
    w4[tid] = x0;
    w4[tid + 256] = x1;
}

// ---------------- AV: weights @ V -> merged-head attn ----------------------
__global__ __launch_bounds__(256)
void av_tc(const float* __restrict__ Wt)
{
    extern __shared__ uint32_t sm[];
    const int tid = threadIdx.x;
    const int bh = blockIdx.z, b = bh>>4, h = bh & 15;
    const int bm = blockIdx.y*128;

    float acc[4][2][4]; ZERO_ACC(acc, 2);
    gemm_bf16<64>(Wt + ((size_t)bh*Sz + bm)*Sz, Sz,
                  g_vt + (size_t)bh*DHz*Sz, Sz, Sz, sm, acc, tid);

    float* stg = (float*)sm;
    stage_acc<64>(stg, acc, tid, 1.f, nullptr);
    __syncthreads();

    for (int i=0;i<8;i++){
        int f = i*256 + tid, r = f>>4, c4 = f&15;
        float4 v = *(float4*)&stg[(size_t)r*68 + c4*4];
        *(float4*)&g_attn[((size_t)b*Sz + bm + r)*Dz + h*DHz + c4*4] = v;
    }
}

// ---------------- dense: out = attn @ W^T + b ------------------------------
__global__ __launch_bounds__(256)
void dense_tc(const float* __restrict__ Wm, const float* __restrict__ bias,
              float* __restrict__ C)
{
    extern __shared__ uint32_t sm[];
    __shared__ float bias_s[128];
    const int tid = threadIdx.x;
    const int bn = blockIdx.x*128, bm = blockIdx.y*128;
    if (tid < 128) bias_s[tid] = bias[bn + tid];

    float acc[4][4][4]; ZERO_ACC(acc, 4);
    gemm_bf16<128>(g_attn + (size_t)bm*Dz, Dz, Wm + (size_t)bn*Dz, Dz, Dz, sm, acc, tid);

    float* stg = (float*)sm;
    stage_acc<128>(stg, acc, tid, 1.f, bias_s);
    __syncthreads();

    for (int i=0;i<16;i++){
        int f = i*256 + tid, r = f>>5, c4 = f&31;
        float4 v = *(float4*)&stg[(size_t)r*132 + c4*4];
        *(float4*)&C[(size_t)(bm + r)*Dz + bn + c4*4] = v;
    }
}

// ---------------------------------------------------------------------------
#define SMEM_128 81920   // 2 stages * (2*A + 2*B) tiles, BN=128
#define SMEM_64  61440   // BN=64

extern "C" void kernel_launch(void* const* d_in, const int* in_sizes, int n_in,
                              void* d_out, int out_size)
{
    const float* q    = (const float*)d_in[0];
    const float* k    = (const float*)d_in[1];
    const float* v    = (const float*)d_in[2];
    const int*   mask = (const int*)  d_in[3];
    const float* wq_w = (const float*)d_in[4];
    const float* wq_b = (const float*)d_in[5];
    const float* wk_w = (const float*)d_in[6];
    const float* wk_b = (const float*)d_in[7];
    const float* wv_w = (const float*)d_in[8];
    const float* wv_b = (const float*)d_in[9];
    const float* dw   = (const float*)d_in[10];
    const float* db   = (const float*)d_in[11];

    float* out     = (float*)d_out;                 // [B,S,D]
    float* weights = out + (size_t)Bz * Sz * Dz;    // [B,H,S,S]

    static int configured = 0;
    if (!configured){
        cudaFuncSetAttribute(proj_tc,   cudaFuncAttributeMaxDynamicSharedMemorySize, SMEM_128);
        cudaFuncSetAttribute(scores_tc, cudaFuncAttributeMaxDynamicSharedMemorySize, SMEM_128);
        cudaFuncSetAttribute(av_tc,     cudaFuncAttributeMaxDynamicSharedMemorySize, SMEM_64);
        cudaFuncSetAttribute(dense_tc,  cudaFuncAttributeMaxDynamicSharedMemorySize, SMEM_128);
        configured = 1;
    }

    dim3 gProj(Dz/128, NROW/128);             // (8, 32)
    proj_tc<<<gProj, 256, SMEM_128>>>(q, wq_w, wq_b, 0);
    proj_tc<<<gProj, 256, SMEM_128>>>(k, wk_w, wk_b, 1);
    proj_tc<<<gProj, 256, SMEM_128>>>(v, wv_w, wv_b, 2);

    dim3 gSc(Sz/128, Sz/128, Bz*Hz);          // (16, 16, 32)
    scores_tc<<<gSc, 256, SMEM_128>>>(mask, weights);

    softmax_kernel<<<Bz*Hz*Sz, 256>>>(weights);

    dim3 gAv(1, Sz/128, Bz*Hz);               // (1, 16, 32)
    av_tc<<<gAv, 256, SMEM_64>>>(weights);

    dim3 gDn(Dz/128, NROW/128);               // (8, 32)
    dense_tc<<<gDn, 256, SMEM_128>>>(dw, db, out);
}